// round 1
// baseline (speedup 1.0000x reference)
#include <cuda_runtime.h>
#include <math.h>

// ---------------- scratch (no allocation allowed -> device globals) ----------------
#define NROWS 8192           // B*N = 8*1024
#define DV    512
__device__ float g_Qp[NROWS * DV];
__device__ float g_Kp[NROWS * DV];
__device__ float g_Vp[NROWS * DV];
__device__ float g_O [NROWS * DV];
__device__ float g_X [NROWS * DV];
__device__ float g_T [NROWS * DV];

// ---------------- SGEMM: C[M,N] = A[M,K] @ W[N,K]^T + bias, optional relu+residual ----------------
// 128x128 block tile, BK=8, 256 threads, 8x8 per-thread micro tile.
__global__ __launch_bounds__(256, 2)
void sgemm_bias_kernel(const float* __restrict__ A, const float* __restrict__ W,
                       const float* __restrict__ bias, float* __restrict__ C,
                       int M, int N, int K, int fuseReluRes)
{
    __shared__ float As[8][128];
    __shared__ float Bs[8][128];

    const int bm = blockIdx.y * 128;
    const int bn = blockIdx.x * 128;
    const int tid = threadIdx.x;

    const int arow = tid >> 1;          // 0..127
    const int acol = (tid & 1) * 4;     // 0 or 4
    const int tr = tid >> 4;            // 0..15
    const int tc = tid & 15;            // 0..15

    const float* Aptr = A + (size_t)(bm + arow) * K + acol;
    const float* Wptr = W + (size_t)(bn + arow) * K + acol;

    float acc[8][8];
#pragma unroll
    for (int i = 0; i < 8; i++)
#pragma unroll
        for (int j = 0; j < 8; j++) acc[i][j] = 0.f;

    for (int k0 = 0; k0 < K; k0 += 8) {
        float4 a = *(const float4*)(Aptr + k0);
        float4 w = *(const float4*)(Wptr + k0);
        As[acol + 0][arow] = a.x; As[acol + 1][arow] = a.y;
        As[acol + 2][arow] = a.z; As[acol + 3][arow] = a.w;
        Bs[acol + 0][arow] = w.x; Bs[acol + 1][arow] = w.y;
        Bs[acol + 2][arow] = w.z; Bs[acol + 3][arow] = w.w;
        __syncthreads();

#pragma unroll
        for (int k = 0; k < 8; k++) {
            float ar[8], br[8];
            *(float4*)(ar)     = *(const float4*)&As[k][tr * 8];
            *(float4*)(ar + 4) = *(const float4*)&As[k][tr * 8 + 4];
            *(float4*)(br)     = *(const float4*)&Bs[k][tc * 8];
            *(float4*)(br + 4) = *(const float4*)&Bs[k][tc * 8 + 4];
#pragma unroll
            for (int i = 0; i < 8; i++)
#pragma unroll
                for (int j = 0; j < 8; j++)
                    acc[i][j] = fmaf(ar[i], br[j], acc[i][j]);
        }
        __syncthreads();
    }

    float bv[8];
#pragma unroll
    for (int j = 0; j < 8; j++) bv[j] = bias[bn + tc * 8 + j];

#pragma unroll
    for (int i = 0; i < 8; i++) {
        const int row = bm + tr * 8 + i;
        const int col = bn + tc * 8;
        float out[8];
#pragma unroll
        for (int j = 0; j < 8; j++) {
            float v = acc[i][j] + bv[j];
            if (fuseReluRes) {
                // residual source is A itself; valid because K == N == 512 here
                v = fmaxf(v, 0.f) + A[(size_t)row * K + col + j];
            }
            out[j] = v;
        }
        *(float4*)&C[(size_t)row * N + col]     = *(float4*)&out[0];
        *(float4*)&C[(size_t)row * N + col + 4] = *(float4*)&out[4];
    }
}

// ---------------- flash attention (fp32, online softmax) + Q residual ----------------
// Per block: one (b, h, 64-query tile). 256 threads as 16(r) x 16(c).
// Thread owns S rows 4r..4r+3, S cols (keys) 4c..4c+3 during S; O dims 4c..4c+3 during PV.
#define APAD 68   // padded row stride (floats): 16B aligned, bank-conflict-free phases
__global__ __launch_bounds__(256, 2)
void attn_kernel(const float* __restrict__ Qp, const float* __restrict__ Kp,
                 const float* __restrict__ Vp, float* __restrict__ O)
{
    extern __shared__ float sm[];
    float* Qs  = sm;                  // [64][APAD]  Q tile (kept whole kernel, residual)
    float* KtP = sm + 64 * APAD;      // [64][APAD]  K^T tile, reused as P tile
    float* Vs  = sm + 2 * 64 * APAD;  // [64][APAD]  V tile

    const int tid = threadIdx.x;
    const int qt = blockIdx.x;   // 0..15
    const int h  = blockIdx.y;   // 0..7
    const int b  = blockIdx.z;   // 0..7
    const int q0 = qt * 64;

    const int r = tid >> 4;      // 0..15
    const int c = tid & 15;      // 0..15

    const float scale = 0.044194173824159216f;  // 1/sqrt(512)

    const float* Qbase = Qp + ((size_t)b * 1024 + q0) * 512 + h * 64;
    const float* Kbase = Kp + ((size_t)b * 1024) * 512 + h * 64;
    const float* Vbase = Vp + ((size_t)b * 1024) * 512 + h * 64;

    // load Q tile (64 rows x 64 cols)
#pragma unroll
    for (int t = 0; t < 4; t++) {
        int idx = t * 256 + tid;
        int row = idx >> 4;
        int c4 = (idx & 15) * 4;
        *(float4*)&Qs[row * APAD + c4] = *(const float4*)&Qbase[(size_t)row * 512 + c4];
    }

    float m_i[4], l_i[4], o_acc[4][4];
#pragma unroll
    for (int i = 0; i < 4; i++) {
        m_i[i] = -1e30f; l_i[i] = 0.f;
#pragma unroll
        for (int j = 0; j < 4; j++) o_acc[i][j] = 0.f;
    }

    for (int ktile = 0; ktile < 16; ktile++) {
        __syncthreads();  // previous iteration's P/Vs reads done; Qs store visible (iter 0)

        // load K tile transposed (KtP[d][k]) and V tile (Vs[k][d])
#pragma unroll
        for (int t = 0; t < 4; t++) {
            int idx = t * 256 + tid;
            int krow = idx >> 4;
            int c4 = (idx & 15) * 4;
            float4 kv = *(const float4*)&Kbase[(size_t)(ktile * 64 + krow) * 512 + c4];
            KtP[(c4 + 0) * APAD + krow] = kv.x;
            KtP[(c4 + 1) * APAD + krow] = kv.y;
            KtP[(c4 + 2) * APAD + krow] = kv.z;
            KtP[(c4 + 3) * APAD + krow] = kv.w;
            *(float4*)&Vs[krow * APAD + c4] =
                *(const float4*)&Vbase[(size_t)(ktile * 64 + krow) * 512 + c4];
        }
        __syncthreads();

        // S = Q @ K^T  (rows 4r+i, keys 4c+j)
        float s[4][4];
#pragma unroll
        for (int i = 0; i < 4; i++)
#pragma unroll
            for (int j = 0; j < 4; j++) s[i][j] = 0.f;

#pragma unroll 2
        for (int kk = 0; kk < 64; kk += 4) {
            float qf[4][4];
#pragma unroll
            for (int i = 0; i < 4; i++) {
                float4 t4 = *(const float4*)&Qs[(4 * r + i) * APAD + kk];
                qf[i][0] = t4.x; qf[i][1] = t4.y; qf[i][2] = t4.z; qf[i][3] = t4.w;
            }
#pragma unroll
            for (int u = 0; u < 4; u++) {
                float4 t4 = *(const float4*)&KtP[(kk + u) * APAD + 4 * c];
#pragma unroll
                for (int i = 0; i < 4; i++) {
                    s[i][0] = fmaf(qf[i][u], t4.x, s[i][0]);
                    s[i][1] = fmaf(qf[i][u], t4.y, s[i][1]);
                    s[i][2] = fmaf(qf[i][u], t4.z, s[i][2]);
                    s[i][3] = fmaf(qf[i][u], t4.w, s[i][3]);
                }
            }
        }

        __syncthreads();  // all S reads of KtP done before overwriting with P

        // online softmax update (per query row; reduce across the 16 c-lanes)
        float p[4][4];
#pragma unroll
        for (int i = 0; i < 4; i++) {
            float mx = -1e30f;
#pragma unroll
            for (int j = 0; j < 4; j++) { s[i][j] *= scale; mx = fmaxf(mx, s[i][j]); }
#pragma unroll
            for (int o = 1; o < 16; o <<= 1)
                mx = fmaxf(mx, __shfl_xor_sync(0xffffffffu, mx, o, 16));
            float mnew = fmaxf(m_i[i], mx);
            float alpha = __expf(m_i[i] - mnew);
            float rs = 0.f;
#pragma unroll
            for (int j = 0; j < 4; j++) { p[i][j] = __expf(s[i][j] - mnew); rs += p[i][j]; }
#pragma unroll
            for (int o = 1; o < 16; o <<= 1)
                rs += __shfl_xor_sync(0xffffffffu, rs, o, 16);
            l_i[i] = l_i[i] * alpha + rs;
            m_i[i] = mnew;
#pragma unroll
            for (int j = 0; j < 4; j++) o_acc[i][j] *= alpha;
        }

        // write P into KtP buffer
#pragma unroll
        for (int i = 0; i < 4; i++)
            *(float4*)&KtP[(4 * r + i) * APAD + 4 * c] =
                make_float4(p[i][0], p[i][1], p[i][2], p[i][3]);
        __syncthreads();

        // O += P @ V  (rows 4r+i, dims 4c+j)
#pragma unroll 2
        for (int k4 = 0; k4 < 16; k4++) {
            float pf[4][4];
#pragma unroll
            for (int i = 0; i < 4; i++) {
                float4 t4 = *(const float4*)&KtP[(4 * r + i) * APAD + 4 * k4];
                pf[i][0] = t4.x; pf[i][1] = t4.y; pf[i][2] = t4.z; pf[i][3] = t4.w;
            }
#pragma unroll
            for (int u = 0; u < 4; u++) {
                float4 v4 = *(const float4*)&Vs[(4 * k4 + u) * APAD + 4 * c];
#pragma unroll
                for (int i = 0; i < 4; i++) {
                    o_acc[i][0] = fmaf(pf[i][u], v4.x, o_acc[i][0]);
                    o_acc[i][1] = fmaf(pf[i][u], v4.y, o_acc[i][1]);
                    o_acc[i][2] = fmaf(pf[i][u], v4.z, o_acc[i][2]);
                    o_acc[i][3] = fmaf(pf[i][u], v4.w, o_acc[i][3]);
                }
            }
        }
    }

    // epilogue: normalize, add Q residual, store (recombined head layout)
    float* Obase = O + ((size_t)b * 1024 + q0) * 512 + h * 64;
#pragma unroll
    for (int i = 0; i < 4; i++) {
        float inv = 1.f / l_i[i];
        float out[4];
#pragma unroll
        for (int j = 0; j < 4; j++)
            out[j] = o_acc[i][j] * inv + Qs[(4 * r + i) * APAD + 4 * c + j];
        *(float4*)&Obase[(size_t)(4 * r + i) * 512 + 4 * c] = *(float4*)&out[0];
    }
}

// ---------------- layernorm over 512 features, one block per row ----------------
__global__ __launch_bounds__(128)
void ln512_kernel(const float* __restrict__ X, const float* __restrict__ g,
                  const float* __restrict__ beta, float* __restrict__ Y)
{
    const int row = blockIdx.x;
    const int tid = threadIdx.x;        // 128 threads, 4 floats each
    const int lane = tid & 31;
    const int wid = tid >> 5;

    float4 v = *(const float4*)&X[(size_t)row * 512 + tid * 4];
    float s  = v.x + v.y + v.z + v.w;
    float sq = v.x * v.x + v.y * v.y + v.z * v.z + v.w * v.w;
#pragma unroll
    for (int o = 16; o; o >>= 1) {
        s  += __shfl_xor_sync(0xffffffffu, s, o);
        sq += __shfl_xor_sync(0xffffffffu, sq, o);
    }
    __shared__ float ws[4], wq[4];
    if (lane == 0) { ws[wid] = s; wq[wid] = sq; }
    __syncthreads();
    float ts = ws[0] + ws[1] + ws[2] + ws[3];
    float tq = wq[0] + wq[1] + wq[2] + wq[3];
    const float mean = ts * (1.f / 512.f);
    const float var  = tq * (1.f / 512.f) - mean * mean;
    const float rstd = rsqrtf(var + 1e-5f);

    float4 gv = *(const float4*)&g[tid * 4];
    float4 bv = *(const float4*)&beta[tid * 4];
    float4 o;
    o.x = (v.x - mean) * rstd * gv.x + bv.x;
    o.y = (v.y - mean) * rstd * gv.y + bv.y;
    o.z = (v.z - mean) * rstd * gv.z + bv.z;
    o.w = (v.w - mean) * rstd * gv.w + bv.w;
    *(float4*)&Y[(size_t)row * 512 + tid * 4] = o;
}

// ---------------- launch ----------------
extern "C" void kernel_launch(void* const* d_in, const int* in_sizes, int n_in,
                              void* d_out, int out_size)
{
    const float* Q   = (const float*)d_in[0];
    const float* K   = (const float*)d_in[1];
    const float* Wq  = (const float*)d_in[2];
    const float* bq  = (const float*)d_in[3];
    const float* Wk  = (const float*)d_in[4];
    const float* bk  = (const float*)d_in[5];
    const float* Wv  = (const float*)d_in[6];
    const float* bv  = (const float*)d_in[7];
    const float* Wo  = (const float*)d_in[8];
    const float* bo  = (const float*)d_in[9];
    const float* g0  = (const float*)d_in[10];
    const float* be0 = (const float*)d_in[11];
    const float* g1  = (const float*)d_in[12];
    const float* be1 = (const float*)d_in[13];
    float* out = (float*)d_out;

    float *Qp, *Kp, *Vp, *Obuf, *Xbuf, *Tbuf;
    cudaGetSymbolAddress((void**)&Qp,   g_Qp);
    cudaGetSymbolAddress((void**)&Kp,   g_Kp);
    cudaGetSymbolAddress((void**)&Vp,   g_Vp);
    cudaGetSymbolAddress((void**)&Obuf, g_O);
    cudaGetSymbolAddress((void**)&Xbuf, g_X);
    cudaGetSymbolAddress((void**)&Tbuf, g_T);

    const int SMEM_ATT = 3 * 64 * APAD * (int)sizeof(float);  // 52224 B
    cudaFuncSetAttribute(attn_kernel, cudaFuncAttributeMaxDynamicSharedMemorySize, SMEM_ATT);

    dim3 gdim(DV / 128, NROWS / 128);   // (4, 64)
    sgemm_bias_kernel<<<gdim, 256>>>(Q, Wq, bq, Qp, NROWS, DV, 512, 0);
    sgemm_bias_kernel<<<gdim, 256>>>(K, Wk, bk, Kp, NROWS, DV, 512, 0);
    sgemm_bias_kernel<<<gdim, 256>>>(K, Wv, bv, Vp, NROWS, DV, 512, 0);

    dim3 adim(16, 8, 8);                // (q-tiles, heads, batch)
    attn_kernel<<<adim, 256, SMEM_ATT>>>(Qp, Kp, Vp, Obuf);

    ln512_kernel<<<NROWS, 128>>>(Obuf, g0, be0, Xbuf);
    sgemm_bias_kernel<<<gdim, 256>>>(Xbuf, Wo, bo, Tbuf, NROWS, DV, 512, 1);
    ln512_kernel<<<NROWS, 128>>>(Tbuf, g1, be1, out);
}

// round 2
// speedup vs baseline: 1.9092x; 1.9092x over previous
#include <cuda_runtime.h>
#include <math.h>

// ---------------- scratch ----------------
#define NROWS 8192
#define DV    512
__device__ float g_Qp[NROWS * DV];
__device__ float g_Kp[NROWS * DV];
__device__ float g_Vp[NROWS * DV];
__device__ float g_O [NROWS * DV];
__device__ float g_X [NROWS * DV];
__device__ float g_T [NROWS * DV];

// ---------------- tf32 helpers ----------------
__device__ __forceinline__ unsigned f2tf(float x) {
    unsigned r; asm("cvt.rna.tf32.f32 %0, %1;" : "=r"(r) : "f"(x)); return r;
}
__device__ __forceinline__ void mma8(float* d, const unsigned* a, const unsigned* b) {
    asm volatile(
        "mma.sync.aligned.m16n8k8.row.col.f32.tf32.tf32.f32 "
        "{%0,%1,%2,%3},{%4,%5,%6,%7},{%8,%9},{%0,%1,%2,%3};"
        : "+f"(d[0]), "+f"(d[1]), "+f"(d[2]), "+f"(d[3])
        : "r"(a[0]), "r"(a[1]), "r"(a[2]), "r"(a[3]), "r"(b[0]), "r"(b[1]));
}

// ---------------- tf32 GEMM: C[M,N] = A[M,K] @ W[N,K]^T + bias (+relu+res) ----------------
// 128x128 block tile, BK=16, 256 threads (8 warps: 4m x 2n), warp tile 32x64.
#define GPAD 20
__global__ __launch_bounds__(256)
void gemm_tf32(const float* __restrict__ A, const float* __restrict__ W,
               const float* __restrict__ bias, float* __restrict__ C,
               int M, int N, int K, int fuseReluRes)
{
    __shared__ unsigned As[128 * GPAD];
    __shared__ unsigned Bs[128 * GPAD];

    const int tid  = threadIdx.x;
    const int lane = tid & 31;
    const int warp = tid >> 5;
    const int wm = warp & 3;     // 0..3 -> m offset wm*32
    const int wn = warp >> 2;    // 0..1 -> n offset wn*64
    const int bm = blockIdx.y * 128;
    const int bn = blockIdx.x * 128;

    const int lrow = tid >> 1;        // 0..127
    const int lk   = (tid & 1) * 8;   // 0 or 8

    float acc[2][8][4];
#pragma unroll
    for (int mi = 0; mi < 2; mi++)
#pragma unroll
        for (int ni = 0; ni < 8; ni++)
#pragma unroll
            for (int j = 0; j < 4; j++) acc[mi][ni][j] = 0.f;

    const int g4 = lane >> 2;   // group id 0..7
    const int t4 = lane & 3;    // 0..3

    for (int k0 = 0; k0 < K; k0 += 16) {
        float4 a0 = *(const float4*)&A[(size_t)(bm + lrow) * K + k0 + lk];
        float4 a1 = *(const float4*)&A[(size_t)(bm + lrow) * K + k0 + lk + 4];
        float4 w0 = *(const float4*)&W[(size_t)(bn + lrow) * K + k0 + lk];
        float4 w1 = *(const float4*)&W[(size_t)(bn + lrow) * K + k0 + lk + 4];
        unsigned* ap = &As[lrow * GPAD + lk];
        unsigned* bp = &Bs[lrow * GPAD + lk];
        ap[0] = f2tf(a0.x); ap[1] = f2tf(a0.y); ap[2] = f2tf(a0.z); ap[3] = f2tf(a0.w);
        ap[4] = f2tf(a1.x); ap[5] = f2tf(a1.y); ap[6] = f2tf(a1.z); ap[7] = f2tf(a1.w);
        bp[0] = f2tf(w0.x); bp[1] = f2tf(w0.y); bp[2] = f2tf(w0.z); bp[3] = f2tf(w0.w);
        bp[4] = f2tf(w1.x); bp[5] = f2tf(w1.y); bp[6] = f2tf(w1.z); bp[7] = f2tf(w1.w);
        __syncthreads();

#pragma unroll
        for (int ks = 0; ks < 2; ks++) {
            unsigned af[2][4];
#pragma unroll
            for (int mi = 0; mi < 2; mi++) {
                const int r = wm * 32 + mi * 16 + g4;
                const int c = ks * 8 + t4;
                af[mi][0] = As[r * GPAD + c];
                af[mi][1] = As[(r + 8) * GPAD + c];
                af[mi][2] = As[r * GPAD + c + 4];
                af[mi][3] = As[(r + 8) * GPAD + c + 4];
            }
#pragma unroll
            for (int ni = 0; ni < 8; ni++) {
                unsigned bf[2];
                const int n = wn * 64 + ni * 8 + g4;
                const int c = ks * 8 + t4;
                bf[0] = Bs[n * GPAD + c];
                bf[1] = Bs[n * GPAD + c + 4];
                mma8(acc[0][ni], af[0], bf);
                mma8(acc[1][ni], af[1], bf);
            }
        }
        __syncthreads();
    }

    // epilogue
#pragma unroll
    for (int mi = 0; mi < 2; mi++) {
#pragma unroll
        for (int ni = 0; ni < 8; ni++) {
            const int row = bm + wm * 32 + mi * 16 + g4;
            const int col = bn + wn * 64 + ni * 8 + 2 * t4;
            const float b0 = bias[col], b1 = bias[col + 1];
            float v00 = acc[mi][ni][0] + b0, v01 = acc[mi][ni][1] + b1;
            float v10 = acc[mi][ni][2] + b0, v11 = acc[mi][ni][3] + b1;
            if (fuseReluRes) {
                v00 = fmaxf(v00, 0.f) + A[(size_t)row * K + col];
                v01 = fmaxf(v01, 0.f) + A[(size_t)row * K + col + 1];
                v10 = fmaxf(v10, 0.f) + A[(size_t)(row + 8) * K + col];
                v11 = fmaxf(v11, 0.f) + A[(size_t)(row + 8) * K + col + 1];
            }
            float2 o0 = make_float2(v00, v01);
            float2 o1 = make_float2(v10, v11);
            *(float2*)&C[(size_t)row * N + col]       = o0;
            *(float2*)&C[(size_t)(row + 8) * N + col] = o1;
        }
    }
}

// ---------------- tf32 flash attention + Q residual ----------------
// 128 threads (4 warps), block = (b, h, 64-query tile). Each warp owns 16 q rows.
// Q fragments pre-scaled + tf32 converted, register-resident whole kernel.
#define SP 68
__global__ __launch_bounds__(128)
void attn_mma(const float* __restrict__ Qp, const float* __restrict__ Kp,
              const float* __restrict__ Vp, float* __restrict__ O)
{
    extern __shared__ unsigned sm[];
    unsigned* Ks = sm;               // [64][SP]  keys x dims (tf32)
    unsigned* Vs = sm + 64 * SP;     // [64][SP]  keys x dims (tf32)
    unsigned* Ps = sm + 2 * 64 * SP; // [64][SP]  probs (tf32), warp-private rows

    const int tid  = threadIdx.x;
    const int lane = tid & 31;
    const int warp = tid >> 5;       // 0..3
    const int g4 = lane >> 2;        // 0..7
    const int t4 = lane & 3;         // 0..3

    const int qt = blockIdx.x, h = blockIdx.y, b = blockIdx.z;
    const int q0 = qt * 64;
    const float scale = 0.044194173824159216f;  // 1/sqrt(512)

    const size_t base = ((size_t)b * 1024) * 512 + h * 64;

    // Q fragments (scaled, tf32), once
    const int qr = q0 + warp * 16 + g4;
    const float* Qrow0 = Qp + base + (size_t)qr * 512;
    const float* Qrow1 = Qrow0 + (size_t)8 * 512;
    unsigned aq[8][4];
#pragma unroll
    for (int ks = 0; ks < 8; ks++) {
        const int c = ks * 8 + t4;
        aq[ks][0] = f2tf(Qrow0[c] * scale);
        aq[ks][1] = f2tf(Qrow1[c] * scale);
        aq[ks][2] = f2tf(Qrow0[c + 4] * scale);
        aq[ks][3] = f2tf(Qrow1[c + 4] * scale);
    }

    float m0 = -1e30f, m1 = -1e30f, l0 = 0.f, l1 = 0.f;
    float o[8][4];
#pragma unroll
    for (int ni = 0; ni < 8; ni++)
#pragma unroll
        for (int j = 0; j < 4; j++) o[ni][j] = 0.f;

    const int ldr = tid >> 1;          // 0..63 (key row)
    const int ldc = (tid & 1) * 32;    // col half

    for (int kt = 0; kt < 16; kt++) {
        __syncthreads();
        // load K/V tile (64 keys x 64 dims), convert to tf32
        const float* Kb = Kp + base + (size_t)(kt * 64 + ldr) * 512 + ldc;
        const float* Vb = Vp + base + (size_t)(kt * 64 + ldr) * 512 + ldc;
        unsigned* kd = &Ks[ldr * SP + ldc];
        unsigned* vd = &Vs[ldr * SP + ldc];
#pragma unroll
        for (int j = 0; j < 8; j++) {
            float4 kv = *(const float4*)&Kb[j * 4];
            float4 vv = *(const float4*)&Vb[j * 4];
            uint4 ku = make_uint4(f2tf(kv.x), f2tf(kv.y), f2tf(kv.z), f2tf(kv.w));
            uint4 vu = make_uint4(f2tf(vv.x), f2tf(vv.y), f2tf(vv.z), f2tf(vv.w));
            *(uint4*)&kd[j * 4] = ku;
            *(uint4*)&vd[j * 4] = vu;
        }
        __syncthreads();

        // S = Qs @ K^T  (16 rows x 64 keys per warp)
        float s[8][4];
#pragma unroll
        for (int ni = 0; ni < 8; ni++)
#pragma unroll
            for (int j = 0; j < 4; j++) s[ni][j] = 0.f;

#pragma unroll
        for (int ks = 0; ks < 8; ks++) {
#pragma unroll
            for (int ni = 0; ni < 8; ni++) {
                unsigned bf[2];
                const int n = ni * 8 + g4;
                const int c = ks * 8 + t4;
                bf[0] = Ks[n * SP + c];
                bf[1] = Ks[n * SP + c + 4];
                mma8(s[ni], aq[ks], bf);
            }
        }

        // online softmax (rows: r = warp*16+g4 and r+8)
        float mx0 = -1e30f, mx1 = -1e30f;
#pragma unroll
        for (int ni = 0; ni < 8; ni++) {
            mx0 = fmaxf(mx0, fmaxf(s[ni][0], s[ni][1]));
            mx1 = fmaxf(mx1, fmaxf(s[ni][2], s[ni][3]));
        }
        mx0 = fmaxf(mx0, __shfl_xor_sync(0xffffffffu, mx0, 1));
        mx0 = fmaxf(mx0, __shfl_xor_sync(0xffffffffu, mx0, 2));
        mx1 = fmaxf(mx1, __shfl_xor_sync(0xffffffffu, mx1, 1));
        mx1 = fmaxf(mx1, __shfl_xor_sync(0xffffffffu, mx1, 2));
        const float M0 = fmaxf(m0, mx0), M1 = fmaxf(m1, mx1);
        const float al0 = __expf(m0 - M0), al1 = __expf(m1 - M1);
        float rs0 = 0.f, rs1 = 0.f;
#pragma unroll
        for (int ni = 0; ni < 8; ni++) {
            s[ni][0] = __expf(s[ni][0] - M0); rs0 += s[ni][0];
            s[ni][1] = __expf(s[ni][1] - M0); rs0 += s[ni][1];
            s[ni][2] = __expf(s[ni][2] - M1); rs1 += s[ni][2];
            s[ni][3] = __expf(s[ni][3] - M1); rs1 += s[ni][3];
        }
        rs0 += __shfl_xor_sync(0xffffffffu, rs0, 1);
        rs0 += __shfl_xor_sync(0xffffffffu, rs0, 2);
        rs1 += __shfl_xor_sync(0xffffffffu, rs1, 1);
        rs1 += __shfl_xor_sync(0xffffffffu, rs1, 2);
        l0 = l0 * al0 + rs0;  l1 = l1 * al1 + rs1;
        m0 = M0;  m1 = M1;
#pragma unroll
        for (int ni = 0; ni < 8; ni++) {
            o[ni][0] *= al0; o[ni][1] *= al0;
            o[ni][2] *= al1; o[ni][3] *= al1;
        }

        // P -> smem (warp-private rows), tf32
        const int pr = warp * 16 + g4;
#pragma unroll
        for (int ni = 0; ni < 8; ni++) {
            const int col = ni * 8 + 2 * t4;
            uint2 p01 = make_uint2(f2tf(s[ni][0]), f2tf(s[ni][1]));
            uint2 p23 = make_uint2(f2tf(s[ni][2]), f2tf(s[ni][3]));
            *(uint2*)&Ps[pr * SP + col]       = p01;
            *(uint2*)&Ps[(pr + 8) * SP + col] = p23;
        }
        __syncwarp();

        // O += P @ V
#pragma unroll
        for (int ks = 0; ks < 8; ks++) {
            unsigned ap[4];
            const int c = ks * 8 + t4;
            ap[0] = Ps[pr * SP + c];
            ap[1] = Ps[(pr + 8) * SP + c];
            ap[2] = Ps[pr * SP + c + 4];
            ap[3] = Ps[(pr + 8) * SP + c + 4];
#pragma unroll
            for (int ni = 0; ni < 8; ni++) {
                unsigned bf[2];
                bf[0] = Vs[(ks * 8 + t4) * SP + ni * 8 + g4];
                bf[1] = Vs[(ks * 8 + t4 + 4) * SP + ni * 8 + g4];
                mma8(o[ni], ap, bf);
            }
        }
    }

    // epilogue: normalize + Q residual, recombined head layout
    const float inv0 = 1.f / l0, inv1 = 1.f / l1;
    float* Ob = O + base + (size_t)qr * 512;
#pragma unroll
    for (int ni = 0; ni < 8; ni++) {
        const int col = ni * 8 + 2 * t4;
        float2 r0 = make_float2(o[ni][0] * inv0 + Qrow0[col],
                                o[ni][1] * inv0 + Qrow0[col + 1]);
        float2 r1 = make_float2(o[ni][2] * inv1 + Qrow1[col],
                                o[ni][3] * inv1 + Qrow1[col + 1]);
        *(float2*)&Ob[col]                    = r0;
        *(float2*)&Ob[(size_t)8 * 512 + col]  = r1;
    }
}

// ---------------- layernorm over 512 features ----------------
__global__ __launch_bounds__(128)
void ln512_kernel(const float* __restrict__ X, const float* __restrict__ g,
                  const float* __restrict__ beta, float* __restrict__ Y)
{
    const int row = blockIdx.x;
    const int tid = threadIdx.x;
    const int lane = tid & 31;
    const int wid = tid >> 5;

    float4 v = *(const float4*)&X[(size_t)row * 512 + tid * 4];
    float s  = v.x + v.y + v.z + v.w;
    float sq = v.x * v.x + v.y * v.y + v.z * v.z + v.w * v.w;
#pragma unroll
    for (int o = 16; o; o >>= 1) {
        s  += __shfl_xor_sync(0xffffffffu, s, o);
        sq += __shfl_xor_sync(0xffffffffu, sq, o);
    }
    __shared__ float ws[4], wq[4];
    if (lane == 0) { ws[wid] = s; wq[wid] = sq; }
    __syncthreads();
    float ts = ws[0] + ws[1] + ws[2] + ws[3];
    float tq = wq[0] + wq[1] + wq[2] + wq[3];
    const float mean = ts * (1.f / 512.f);
    const float var  = tq * (1.f / 512.f) - mean * mean;
    const float rstd = rsqrtf(var + 1e-5f);

    float4 gv = *(const float4*)&g[tid * 4];
    float4 bv = *(const float4*)&beta[tid * 4];
    float4 o;
    o.x = (v.x - mean) * rstd * gv.x + bv.x;
    o.y = (v.y - mean) * rstd * gv.y + bv.y;
    o.z = (v.z - mean) * rstd * gv.z + bv.z;
    o.w = (v.w - mean) * rstd * gv.w + bv.w;
    *(float4*)&Y[(size_t)row * 512 + tid * 4] = o;
}

// ---------------- launch ----------------
extern "C" void kernel_launch(void* const* d_in, const int* in_sizes, int n_in,
                              void* d_out, int out_size)
{
    const float* Q   = (const float*)d_in[0];
    const float* K   = (const float*)d_in[1];
    const float* Wq  = (const float*)d_in[2];
    const float* bq  = (const float*)d_in[3];
    const float* Wk  = (const float*)d_in[4];
    const float* bk  = (const float*)d_in[5];
    const float* Wv  = (const float*)d_in[6];
    const float* bv  = (const float*)d_in[7];
    const float* Wo  = (const float*)d_in[8];
    const float* bo  = (const float*)d_in[9];
    const float* g0  = (const float*)d_in[10];
    const float* be0 = (const float*)d_in[11];
    const float* g1  = (const float*)d_in[12];
    const float* be1 = (const float*)d_in[13];
    float* out = (float*)d_out;

    float *Qp, *Kp, *Vp, *Obuf, *Xbuf, *Tbuf;
    cudaGetSymbolAddress((void**)&Qp,   g_Qp);
    cudaGetSymbolAddress((void**)&Kp,   g_Kp);
    cudaGetSymbolAddress((void**)&Vp,   g_Vp);
    cudaGetSymbolAddress((void**)&Obuf, g_O);
    cudaGetSymbolAddress((void**)&Xbuf, g_X);
    cudaGetSymbolAddress((void**)&Tbuf, g_T);

    const int SMEM_ATT = 3 * 64 * SP * (int)sizeof(unsigned);  // 52224 B
    cudaFuncSetAttribute(attn_mma, cudaFuncAttributeMaxDynamicSharedMemorySize, SMEM_ATT);

    dim3 gdim(DV / 128, NROWS / 128);   // (4, 64)
    gemm_tf32<<<gdim, 256>>>(Q, Wq, bq, Qp, NROWS, DV, 512, 0);
    gemm_tf32<<<gdim, 256>>>(K, Wk, bk, Kp, NROWS, DV, 512, 0);
    gemm_tf32<<<gdim, 256>>>(K, Wv, bv, Vp, NROWS, DV, 512, 0);

    dim3 adim(16, 8, 8);
    attn_mma<<<adim, 128, SMEM_ATT>>>(Qp, Kp, Vp, Obuf);

    ln512_kernel<<<NROWS, 128>>>(Obuf, g0, be0, Xbuf);
    gemm_tf32<<<gdim, 256>>>(Xbuf, Wo, bo, Tbuf, NROWS, DV, 512, 1);
    ln512_kernel<<<NROWS, 128>>>(Tbuf, g1, be1, out);
}